// round 3
// baseline (speedup 1.0000x reference)
#include <cuda_runtime.h>
#include <cstdint>
#include <float.h>

#define MAXVAL   5843
#define BATCH    4
#define TOP_K    200
#define STEP     30
#define NSTEPS   189           // ceil((5843-200)/30)
#define NTHREADS 256

__inline__ __device__ float warp_max(float v) {
    #pragma unroll
    for (int o = 16; o > 0; o >>= 1)
        v = fmaxf(v, __shfl_xor_sync(0xFFFFFFFFu, v, o));
    return v;
}
__inline__ __device__ float warp_sum(float v) {
    #pragma unroll
    for (int o = 16; o > 0; o >>= 1)
        v += __shfl_xor_sync(0xFFFFFFFFu, v, o);
    return v;
}

__global__ __launch_bounds__(NTHREADS)
void masked_softmax_kernel(const float* __restrict__ X, float* __restrict__ out) {
    const int row = blockIdx.x;                 // 0 .. BATCH*MAXVAL-1
    const int q   = row % MAXVAL;
    const int s   = min(q, NSTEPS - 1) * STEP;  // window start column

    const float* __restrict__ xrow = X   + (size_t)row * MAXVAL;
    float*       __restrict__ orow = out + (size_t)row * MAXVAL;

    __shared__ float sh_prob[TOP_K];
    __shared__ float red[8];

    const int t    = threadIdx.x;
    const int warp = t >> 5;
    const int lane = t & 31;

    // ---- load window value (threads >= TOP_K contribute -inf / 0) ----
    float v = (t < TOP_K) ? xrow[s + t] : -FLT_MAX;

    // ---- block max ----
    float m = warp_max(v);
    if (lane == 0) red[warp] = m;
    __syncthreads();
    if (warp == 0) {
        float r = (lane < 8) ? red[lane] : -FLT_MAX;
        r = warp_max(r);
        if (lane == 0) red[0] = r;
    }
    __syncthreads();
    m = red[0];
    __syncthreads();

    // ---- block sum of exp ----
    float e = (t < TOP_K) ? __expf(v - m) : 0.0f;
    float ssum = warp_sum(e);
    if (lane == 0) red[warp] = ssum;
    __syncthreads();
    if (warp == 0) {
        float r = (lane < 8) ? red[lane] : 0.0f;
        r = warp_sum(r);
        if (lane == 0) red[0] = r;
    }
    __syncthreads();
    const float inv = __frcp_rn(red[0]);

    if (t < TOP_K) sh_prob[t] = e * inv;
    __syncthreads();

    // ---- stream the full row: zeros outside the window, probs inside ----
    // Align to 16B for float4 stores (row base is only 4B-aligned).
    const uintptr_t addr = (uintptr_t)orow;
    const int head = (int)(((16u - (addr & 15u)) & 15u) >> 2);   // 0..3 scalar elems

    for (int j = t; j < head; j += NTHREADS) {
        const int d = j - s;
        orow[j] = ((unsigned)d < (unsigned)TOP_K) ? sh_prob[d] : 0.0f;
    }

    const int nvec = (MAXVAL - head) >> 2;
    float4* __restrict__ o4 = (float4*)(orow + head);
    for (int k = t; k < nvec; k += NTHREADS) {
        const int j = head + (k << 2);
        float4 w;
        int d0 = j - s, d1 = d0 + 1, d2 = d0 + 2, d3 = d0 + 3;
        w.x = ((unsigned)d0 < (unsigned)TOP_K) ? sh_prob[d0] : 0.0f;
        w.y = ((unsigned)d1 < (unsigned)TOP_K) ? sh_prob[d1] : 0.0f;
        w.z = ((unsigned)d2 < (unsigned)TOP_K) ? sh_prob[d2] : 0.0f;
        w.w = ((unsigned)d3 < (unsigned)TOP_K) ? sh_prob[d3] : 0.0f;
        __stcs(&o4[k], w);   // streaming store: write-once data, skip L2 retention
    }

    for (int j = head + (nvec << 2) + t; j < MAXVAL; j += NTHREADS) {
        const int d = j - s;
        orow[j] = ((unsigned)d < (unsigned)TOP_K) ? sh_prob[d] : 0.0f;
    }
}

extern "C" void kernel_launch(void* const* d_in, const int* in_sizes, int n_in,
                              void* d_out, int out_size) {
    const float* X = (const float*)d_in[0];
    float* out = (float*)d_out;
    (void)in_sizes; (void)n_in; (void)out_size;
    masked_softmax_kernel<<<BATCH * MAXVAL, NTHREADS>>>(X, out);
}

// round 5
// speedup vs baseline: 1.0031x; 1.0031x over previous
#include <cuda_runtime.h>
#include <cstdint>
#include <float.h>

#define MAXVAL   5843
#define BATCH    4
#define TOP_K    200
#define STEP     30
#define NSTEPS   189           // ceil((5843-200)/30)
#define NTHREADS 256

__inline__ __device__ float warp_max(float v) {
    #pragma unroll
    for (int o = 16; o > 0; o >>= 1)
        v = fmaxf(v, __shfl_xor_sync(0xFFFFFFFFu, v, o));
    return v;
}
__inline__ __device__ float warp_sum(float v) {
    #pragma unroll
    for (int o = 16; o > 0; o >>= 1)
        v += __shfl_xor_sync(0xFFFFFFFFu, v, o);
    return v;
}

// Branch-free zero fill of orow[lo..hi) using 16B-aligned streaming stores.
__inline__ __device__ void fill_zero(float* __restrict__ orow, int lo, int hi, int t) {
    if (lo >= hi) return;
    const uintptr_t base = (uintptr_t)(orow + lo);
    int head = (int)(((16u - (base & 15u)) & 15u) >> 2);
    if (head > hi - lo) head = hi - lo;

    // scalar head (0..3 elems)
    if (t < head) orow[lo + t] = 0.0f;

    const int lo2  = lo + head;
    const int nvec = (hi - lo2) >> 2;
    float4* __restrict__ p = (float4*)(orow + lo2);
    const float4 z = make_float4(0.0f, 0.0f, 0.0f, 0.0f);
    for (int k = t; k < nvec; k += NTHREADS)
        __stcs(&p[k], z);

    // scalar tail (0..3 elems)
    const int tail_lo = lo2 + (nvec << 2);
    if (t < hi - tail_lo) orow[tail_lo + t] = 0.0f;
}

__global__ __launch_bounds__(NTHREADS)
void masked_softmax_kernel(const float* __restrict__ X, float* __restrict__ out) {
    const int row = blockIdx.x;                 // 0 .. BATCH*MAXVAL-1
    const int q   = row % MAXVAL;
    const int s   = min(q, NSTEPS - 1) * STEP;  // window start column (<= 5640)

    const float* __restrict__ xrow = X   + (size_t)row * MAXVAL;
    float*       __restrict__ orow = out + (size_t)row * MAXVAL;

    __shared__ float sh_prob[TOP_K];
    __shared__ float red[8];

    const int t    = threadIdx.x;
    const int warp = t >> 5;
    const int lane = t & 31;

    // ---- load window value (threads >= TOP_K contribute -inf / 0) ----
    float v = (t < TOP_K) ? xrow[s + t] : -FLT_MAX;

    // ---- block max ----
    float m = warp_max(v);
    if (lane == 0) red[warp] = m;
    __syncthreads();
    if (warp == 0) {
        float r = (lane < 8) ? red[lane] : -FLT_MAX;
        r = warp_max(r);
        if (lane == 0) red[0] = r;
    }
    __syncthreads();
    m = red[0];
    __syncthreads();

    // ---- block sum of exp ----
    float e = (t < TOP_K) ? __expf(v - m) : 0.0f;
    float ssum = warp_sum(e);
    if (lane == 0) red[warp] = ssum;
    __syncthreads();
    if (warp == 0) {
        float r = (lane < 8) ? red[lane] : 0.0f;
        r = warp_sum(r);
        if (lane == 0) red[0] = r;
    }
    __syncthreads();
    const float inv = __frcp_rn(red[0]);

    if (t < TOP_K) sh_prob[t] = e * inv;
    __syncthreads();

    // ---- region-split row write ----
    // [0, s)           : zeros  (bulk, branch-free)
    // [s, s+TOP_K)     : probabilities from smem (scalar, 800 B)
    // [s+TOP_K, MAXVAL): zeros  (short tail region)
    fill_zero(orow, 0, s, t);

    if (t < TOP_K) orow[s + t] = sh_prob[t];

    fill_zero(orow, s + TOP_K, MAXVAL, t);
}

extern "C" void kernel_launch(void* const* d_in, const int* in_sizes, int n_in,
                              void* d_out, int out_size) {
    const float* X = (const float*)d_in[0];
    float* out = (float*)d_out;
    (void)in_sizes; (void)n_in; (void)out_size;
    masked_softmax_kernel<<<BATCH * MAXVAL, NTHREADS>>>(X, out);
}